// round 3
// baseline (speedup 1.0000x reference)
#include <cuda_runtime.h>
#include <cuda_bf16.h>
#include <math.h>

// ---------------- problem constants ----------------
#define M_ATOMS 8192
#define NB      16
#define NPG     512
#define FD      128
#define HD      64
#define DD      16
#define SE      95
#define EH      159
#define TABN2   8192
#define INVD2   59.0f        // covers d <= 138.8 (max possible = 138.6)
#define SPAD    20

// ---------------- device scratch ----------------
__device__ float2 d_tab2[TABN2 + 1];
__device__ float d_srcraw[M_ATOMS * DD];
__device__ float d_gmean[NB * DD];
__device__ float d_shell[M_ATOMS * SE];
__device__ float d_pa[M_ATOMS];
// pre-scaled (LayerNorm-folded) weights + column sums
__device__ float d_w1p[FD * HD];  __device__ float d_c1s[HD]; __device__ float d_c0s[HD];
__device__ float d_sw1p[SE * HD]; __device__ float d_c1e[HD]; __device__ float d_c0e[HD];
__device__ float d_ew1p[EH * HD]; __device__ float d_c1h[HD]; __device__ float d_c0h[HD];

// ---------------- scalar kernel function f(d) ----------------
__device__ __forceinline__ float kerf(float d, float scr,
                                      const float* kw1, const float* kb1,
                                      const float* kw2, const float* kb2) {
    float base = expf(-scr * d) / fmaxf(d, 1e-6f);
    float g0 = d * (1.0f / 5.0f);
    float g1 = d * (1.0f / 40.0f);
    float rbf[8];
#pragma unroll
    for (int r = 0; r < 8; r++) {
        float dc = d - (5.0f + 5.0f * (float)r);
        rbf[r] = expf(-0.04f * dc * dc);
    }
    float out = kb2[0];
#pragma unroll 4
    for (int k = 0; k < 32; k++) {
        float a = kb1[k];
        a = fmaf(g0, kw1[0 * 32 + k], a);
        a = fmaf(g1, kw1[1 * 32 + k], a);
#pragma unroll
        for (int r = 0; r < 8; r++) a = fmaf(rbf[r], kw1[(2 + r) * 32 + k], a);
        float sl = a / (1.0f + expf(-a));
        out = fmaf(sl, kw2[k], out);
    }
    return base * (1.0f + tanhf(out));
}

// ---------------- K0: build float2 lerp table ----------------
__global__ void table_kernel(const float* __restrict__ k_screen,
                             const float* __restrict__ kw1, const float* __restrict__ kb1,
                             const float* __restrict__ kw2, const float* __restrict__ kb2) {
    int i = blockIdx.x * blockDim.x + threadIdx.x;
    if (i > TABN2) return;
    float scr = log1pf(expf(k_screen[0]));
    float f0 = kerf((float)i / INVD2, scr, kw1, kb1, kw2, kb2);
    float f1 = kerf((float)(i + 1) / INVD2, scr, kw1, kb1, kw2, kb2);
    d_tab2[i] = make_float2(f0, f1 - f0);
}

// ---------------- K0b: prep pre-scaled weights ----------------
// grid = 3, block = 64 (one thread per hidden column)
__global__ void prep_kernel(const float* __restrict__ ing, const float* __restrict__ inb,
                            const float* __restrict__ w1,
                            const float* __restrict__ seg, const float* __restrict__ seb,
                            const float* __restrict__ sw1,
                            const float* __restrict__ eg,  const float* __restrict__ ebv,
                            const float* __restrict__ ew1) {
    int h = threadIdx.x;
    int which = blockIdx.x;
    const float* g; const float* b; const float* w; float* wp; float* c1; float* c0; int M;
    if (which == 0)      { g = ing; b = inb; w = w1;  wp = d_w1p;  c1 = d_c1s; c0 = d_c0s; M = FD; }
    else if (which == 1) { g = seg; b = seb; w = sw1; wp = d_sw1p; c1 = d_c1e; c0 = d_c0e; M = SE; }
    else                 { g = eg;  b = ebv; w = ew1; wp = d_ew1p; c1 = d_c1h; c0 = d_c0h; M = EH; }
    float s1 = 0.0f, s0 = 0.0f;
    for (int m = 0; m < M; m++) {
        float wv = w[m * HD + h];
        float sc = g[m] * wv;
        wp[m * HD + h] = sc;
        s1 += sc;
        s0 += b[m] * wv;
    }
    c1[h] = s1; c0[h] = s0;
}

// ---------------- K1: source MLP (tiled, 32 atoms/block) ----------------
__global__ __launch_bounds__(256) void src_kernel(
    const float* __restrict__ x,
    const float* __restrict__ b1, const float* __restrict__ w2, const float* __restrict__ b2,
    const float* __restrict__ lg, const float* __restrict__ lb) {
    __shared__ float xs[32 * 132];
    __shared__ float hs[32 * 68];
    __shared__ float os[32 * 17];
    __shared__ float mnA[32], rsA[32], mn2[32], rs2[32];
    int t = threadIdx.x, w = t >> 5, lane = t & 31;
    int i0 = blockIdx.x * 32;

    // phase A: load x tile + per-atom LN stats
#pragma unroll
    for (int aa = 0; aa < 4; aa++) {
        int a = w * 4 + aa;
        const float* xr = x + (size_t)(i0 + a) * FD;
        float s = 0.0f, q = 0.0f;
#pragma unroll
        for (int k = 0; k < 4; k++) {
            float v = xr[lane + 32 * k];
            xs[a * 132 + lane + 32 * k] = v;
            s += v; q += v * v;
        }
#pragma unroll
        for (int o = 16; o; o >>= 1) {
            s += __shfl_xor_sync(0xffffffffu, s, o);
            q += __shfl_xor_sync(0xffffffffu, q, o);
        }
        if (lane == 0) {
            float mn = s * (1.0f / FD);
            float vr = q * (1.0f / FD) - mn * mn;
            mnA[a] = mn; rsA[a] = rsqrtf(vr + 1e-5f);
        }
    }
    __syncthreads();

    int a = t >> 3, sub = t & 7, h0 = sub * 8;
    // phase B: hidden layer with folded LN
    {
        float acc[8];
#pragma unroll
        for (int k = 0; k < 8; k++) acc[k] = 0.0f;
#pragma unroll 4
        for (int m = 0; m < FD; m++) {
            float xv = xs[a * 132 + m];
            float4 wa = __ldg((const float4*)(d_w1p + m * HD + h0));
            float4 wb = __ldg((const float4*)(d_w1p + m * HD + h0 + 4));
            acc[0] = fmaf(xv, wa.x, acc[0]); acc[1] = fmaf(xv, wa.y, acc[1]);
            acc[2] = fmaf(xv, wa.z, acc[2]); acc[3] = fmaf(xv, wa.w, acc[3]);
            acc[4] = fmaf(xv, wb.x, acc[4]); acc[5] = fmaf(xv, wb.y, acc[5]);
            acc[6] = fmaf(xv, wb.z, acc[6]); acc[7] = fmaf(xv, wb.w, acc[7]);
        }
        float mn = mnA[a], rstd = rsA[a];
#pragma unroll
        for (int hh = 0; hh < 8; hh++) {
            int h = h0 + hh;
            float pre = rstd * (acc[hh] - mn * __ldg(&d_c1s[h])) + __ldg(&d_c0s[h]) + __ldg(&b1[h]);
            hs[a * 68 + h] = pre / (1.0f + expf(-pre));
        }
    }
    __syncthreads();

    // phase C: output layer (2 outputs per thread)
    {
        float o0 = __ldg(&b2[sub]), o1 = __ldg(&b2[sub + 8]);
#pragma unroll 4
        for (int k = 0; k < HD; k++) {
            float hv = hs[a * 68 + k];
            o0 = fmaf(hv, __ldg(&w2[k * DD + sub]), o0);
            o1 = fmaf(hv, __ldg(&w2[k * DD + sub + 8]), o1);
        }
        os[a * 17 + sub] = o0; os[a * 17 + sub + 8] = o1;
    }
    __syncthreads();

    // phase D: LN(16) + write
    if (t < 32) {
        float s = 0.0f, q = 0.0f;
#pragma unroll
        for (int c = 0; c < DD; c++) { float v = os[t * 17 + c]; s += v; q += v * v; }
        float mn = s * (1.0f / DD);
        float vr = q * (1.0f / DD) - mn * mn;
        mn2[t] = mn; rs2[t] = rsqrtf(vr + 1e-5f);
    }
    __syncthreads();
    for (int e = t; e < 512; e += 256) {
        int a2 = e >> 4, c = e & 15;
        float y = (os[a2 * 17 + c] - mn2[a2]) * rs2[a2] * __ldg(&lg[c]) + __ldg(&lb[c]);
        d_srcraw[(size_t)(i0 + a2) * DD + c] = y;
    }
}

// ---------------- K2: per-graph mean of src ----------------
__global__ void mean_kernel() {
    int g = blockIdx.x;
    int t = threadIdx.x;          // 256
    int c = t & 15, r0 = t >> 4;
    float a = 0.0f;
    for (int j = r0; j < NPG; j += 16)
        a += d_srcraw[(size_t)(g * NPG + j) * DD + c];
    __shared__ float sm[256];
    sm[t] = a;
    __syncthreads();
    if (t < DD) {
        float s = 0.0f;
#pragma unroll
        for (int k = 0; k < 16; k++) s += sm[k * 16 + t];
        d_gmean[g * DD + t] = s * (1.0f / NPG);
    }
}

// ---------------- K3: pairwise shell statistics ----------------
// 128 threads = 4 warps; 4 atoms per warp (8 j-lanes per atom) -> 16 atoms/block
#define GRED(v) { v += __shfl_down_sync(0xffffffffu, v, 4); \
                  v += __shfl_down_sync(0xffffffffu, v, 2); \
                  v += __shfl_down_sync(0xffffffffu, v, 1); }

__global__ __launch_bounds__(128, 3) void pair_kernel(const float* __restrict__ pos) {
    __shared__ float sTf[NPG * SPAD];
    __shared__ float px[NPG], py[NPG], pz[NPG];
    int g    = blockIdx.x >> 5;   // 32 blocks per graph
    int blk  = blockIdx.x & 31;   // 16 atoms per block
    int t    = threadIdx.x;
    int gbase = g * NPG;

    for (int idx = t; idx < NPG * DD; idx += 128) {
        int j = idx >> 4, c = idx & 15;
        sTf[j * SPAD + c] = d_srcraw[(size_t)(gbase + j) * DD + c] - __ldg(&d_gmean[g * DD + c]);
    }
    for (int j = t; j < NPG; j += 128) {
        const float* p = pos + (size_t)(gbase + j) * 3;
        px[j] = p[0]; py[j] = p[1]; pz[j] = p[2];
    }
    __syncthreads();

    int w = t >> 5, lane = t & 31;
    int a = lane >> 3, sub = lane & 7;
    int li = blk * 16 + w * 4 + a;
    float xi = px[li], yi = py[li], zi = pz[li];

    const float4* sT4 = (const float4*)sTf;

    float am0[16], am1[16], am2[16], am3[16], am4[16];
    float ac[5], ad[5], ad2[5];
#pragma unroll
    for (int c = 0; c < 16; c++) { am0[c]=0.f; am1[c]=0.f; am2[c]=0.f; am3[c]=0.f; am4[c]=0.f; }
#pragma unroll
    for (int s = 0; s < 5; s++) { ac[s]=0.f; ad[s]=0.f; ad2[s]=0.f; }

#pragma unroll 4
    for (int it = 0; it < 64; it++) {
        int j = sub + it * 8;
        float dx = px[j] - xi, dy = py[j] - yi, dz = pz[j] - zi;
        float dsq = fmaf(dx, dx, fmaf(dy, dy, fmaf(dz, dz, 1e-12f)));
        float d = sqrtf(dsq);
        float tt = d * INVD2;
        int k = (int)tt; if (k > TABN2 - 1) k = TABN2 - 1;
        float fr = tt - (float)k;
        float2 tv = __ldg(&d_tab2[k]);
        float wv = fmaf(fr, tv.y, tv.x);
        float m0 = (d >= 5.0f  && d < 10.0f) ? 1.0f : 0.0f;
        float m1 = (d >= 10.0f && d < 20.0f) ? 1.0f : 0.0f;
        float m2 = (d >= 20.0f && d < 40.0f) ? 1.0f : 0.0f;
        float m3 = (d >= 40.0f && d < 80.0f) ? 1.0f : 0.0f;
        float m4 = (d >= 80.0f) ? 1.0f : 0.0f;
        float w0 = wv * m0, w1 = wv * m1, w2 = wv * m2, w3 = wv * m3, w4 = wv * m4;
        float dd = d * d;
        ac[0] += m0; ad[0] = fmaf(m0, d, ad[0]); ad2[0] = fmaf(m0, dd, ad2[0]);
        ac[1] += m1; ad[1] = fmaf(m1, d, ad[1]); ad2[1] = fmaf(m1, dd, ad2[1]);
        ac[2] += m2; ad[2] = fmaf(m2, d, ad[2]); ad2[2] = fmaf(m2, dd, ad2[2]);
        ac[3] += m3; ad[3] = fmaf(m3, d, ad[3]); ad2[3] = fmaf(m3, dd, ad2[3]);
        ac[4] += m4; ad[4] = fmaf(m4, d, ad[4]); ad2[4] = fmaf(m4, dd, ad2[4]);
        float4 s0 = sT4[j * 5 + 0];
        float4 s1 = sT4[j * 5 + 1];
        float4 s2 = sT4[j * 5 + 2];
        float4 s3 = sT4[j * 5 + 3];
        float sv[16] = { s0.x, s0.y, s0.z, s0.w, s1.x, s1.y, s1.z, s1.w,
                         s2.x, s2.y, s2.z, s2.w, s3.x, s3.y, s3.z, s3.w };
#pragma unroll
        for (int c = 0; c < 16; c++) {
            am0[c] = fmaf(w0, sv[c], am0[c]);
            am1[c] = fmaf(w1, sv[c], am1[c]);
            am2[c] = fmaf(w2, sv[c], am2[c]);
            am3[c] = fmaf(w3, sv[c], am3[c]);
            am4[c] = fmaf(w4, sv[c], am4[c]);
        }
    }

#pragma unroll
    for (int s = 0; s < 5; s++) { GRED(ac[s]); GRED(ad[s]); GRED(ad2[s]); }
#pragma unroll
    for (int c = 0; c < 16; c++) { GRED(am0[c]); GRED(am1[c]); GRED(am2[c]); GRED(am3[c]); GRED(am4[c]); }

    if (sub == 0) {
        int i = gbase + li;
        float* o = d_shell + (size_t)i * SE;
        float den, cnt;
        cnt = ac[0]; den = fmaxf(cnt, 1.0f);
#pragma unroll
        for (int c = 0; c < 16; c++) o[0*19 + c] = am0[c] / den;
        o[0*19+16] = cnt; o[0*19+17] = ad[0] / den; o[0*19+18] = sqrtf(ad2[0] / den + 1e-12f);
        cnt = ac[1]; den = fmaxf(cnt, 1.0f);
#pragma unroll
        for (int c = 0; c < 16; c++) o[1*19 + c] = am1[c] / den;
        o[1*19+16] = cnt; o[1*19+17] = ad[1] / den; o[1*19+18] = sqrtf(ad2[1] / den + 1e-12f);
        cnt = ac[2]; den = fmaxf(cnt, 1.0f);
#pragma unroll
        for (int c = 0; c < 16; c++) o[2*19 + c] = am2[c] / den;
        o[2*19+16] = cnt; o[2*19+17] = ad[2] / den; o[2*19+18] = sqrtf(ad2[2] / den + 1e-12f);
        cnt = ac[3]; den = fmaxf(cnt, 1.0f);
#pragma unroll
        for (int c = 0; c < 16; c++) o[3*19 + c] = am3[c] / den;
        o[3*19+16] = cnt; o[3*19+17] = ad[3] / den; o[3*19+18] = sqrtf(ad2[3] / den + 1e-12f);
        cnt = ac[4]; den = fmaxf(cnt, 1.0f);
#pragma unroll
        for (int c = 0; c < 16; c++) o[4*19 + c] = am4[c] / den;
        o[4*19+16] = cnt; o[4*19+17] = ad[4] / den; o[4*19+18] = sqrtf(ad2[4] / den + 1e-12f);
    }
}

// ---------------- K4: energy head (tiled, 32 atoms/block) ----------------
__global__ __launch_bounds__(256) void energy_kernel(
    const float* __restrict__ sb1, const float* __restrict__ sw2, const float* __restrict__ sb2,
    const float* __restrict__ eb1, const float* __restrict__ ew2, const float* __restrict__ eb2,
    const float* __restrict__ far_gate, const float* __restrict__ escale) {
    __shared__ float s_sh[32 * 97];   // raw shell tile
    __shared__ float eb4[32 * 68];    // [src, emb, src*emb, src-emb]
    __shared__ float hs[32 * 68];     // silu'd hidden
    __shared__ float sc[32 * 17];     // centered src
    __shared__ float es[32 * 17];     // emb
    __shared__ float mnS[32], rsS[32], mnE[32], rsE[32];
    int t = threadIdx.x, w = t >> 5, lane = t & 31;
    int i0 = blockIdx.x * 32;
    int g = i0 >> 9;

    // load shell tile
    for (int e = t; e < 32 * SE; e += 256) {
        int a = e / SE, m = e - a * SE;
        s_sh[a * 97 + m] = d_shell[(size_t)(i0 + a) * SE + m];
    }
    // centered src
    for (int e = t; e < 32 * DD; e += 256) {
        int a = e >> 4, c = e & 15;
        sc[a * 17 + c] = d_srcraw[(size_t)(i0 + a) * DD + c] - __ldg(&d_gmean[g * DD + c]);
    }
    __syncthreads();

    // LN stats over shell (95) : warp handles 4 atoms
#pragma unroll
    for (int aa = 0; aa < 4; aa++) {
        int a = w * 4 + aa;
        float s = 0.0f, q = 0.0f;
        for (int m = lane; m < SE; m += 32) { float v = s_sh[a * 97 + m]; s += v; q += v * v; }
#pragma unroll
        for (int o = 16; o; o >>= 1) {
            s += __shfl_xor_sync(0xffffffffu, s, o);
            q += __shfl_xor_sync(0xffffffffu, q, o);
        }
        if (lane == 0) {
            float mn = s * (1.0f / SE);
            float vr = q * (1.0f / SE) - mn * mn;
            mnS[a] = mn; rsS[a] = rsqrtf(vr + 1e-5f);
        }
    }
    __syncthreads();

    int a = t >> 3, sub = t & 7, h0 = sub * 8;
    // se hidden with folded LN
    {
        float acc[8];
#pragma unroll
        for (int k = 0; k < 8; k++) acc[k] = 0.0f;
#pragma unroll 4
        for (int m = 0; m < SE; m++) {
            float v = s_sh[a * 97 + m];
            float4 wa = __ldg((const float4*)(d_sw1p + m * HD + h0));
            float4 wb = __ldg((const float4*)(d_sw1p + m * HD + h0 + 4));
            acc[0] = fmaf(v, wa.x, acc[0]); acc[1] = fmaf(v, wa.y, acc[1]);
            acc[2] = fmaf(v, wa.z, acc[2]); acc[3] = fmaf(v, wa.w, acc[3]);
            acc[4] = fmaf(v, wb.x, acc[4]); acc[5] = fmaf(v, wb.y, acc[5]);
            acc[6] = fmaf(v, wb.z, acc[6]); acc[7] = fmaf(v, wb.w, acc[7]);
        }
        float mn = mnS[a], rstd = rsS[a];
#pragma unroll
        for (int hh = 0; hh < 8; hh++) {
            int h = h0 + hh;
            float pre = rstd * (acc[hh] - mn * __ldg(&d_c1e[h])) + __ldg(&d_c0e[h]) + __ldg(&sb1[h]);
            hs[a * 68 + h] = pre / (1.0f + expf(-pre));
        }
    }
    __syncthreads();

    // emb: 2 outputs per thread
    {
        float o0 = __ldg(&sb2[sub]), o1 = __ldg(&sb2[sub + 8]);
#pragma unroll 4
        for (int k = 0; k < HD; k++) {
            float hv = hs[a * 68 + k];
            o0 = fmaf(hv, __ldg(&sw2[k * DD + sub]), o0);
            o1 = fmaf(hv, __ldg(&sw2[k * DD + sub + 8]), o1);
        }
        es[a * 17 + sub] = o0; es[a * 17 + sub + 8] = o1;
    }
    __syncthreads();

    // build first 64 dims of ein
    for (int e = t; e < 32 * 64; e += 256) {
        int a2 = e >> 6, c = e & 63;
        int cc = c & 15, seg4 = c >> 4;
        float sv = sc[a2 * 17 + cc], ev = es[a2 * 17 + cc];
        float r;
        if (seg4 == 0) r = sv;
        else if (seg4 == 1) r = ev;
        else if (seg4 == 2) r = sv * ev;
        else r = sv - ev;
        eb4[a2 * 68 + c] = r;
    }
    __syncthreads();

    // LN stats over ein (159)
#pragma unroll
    for (int aa = 0; aa < 4; aa++) {
        int a2 = w * 4 + aa;
        float s = 0.0f, q = 0.0f;
        for (int m = lane; m < 64; m += 32) { float v = eb4[a2 * 68 + m]; s += v; q += v * v; }
        for (int m = lane; m < SE; m += 32) { float v = s_sh[a2 * 97 + m]; s += v; q += v * v; }
#pragma unroll
        for (int o = 16; o; o >>= 1) {
            s += __shfl_xor_sync(0xffffffffu, s, o);
            q += __shfl_xor_sync(0xffffffffu, q, o);
        }
        if (lane == 0) {
            float mn = s * (1.0f / EH);
            float vr = q * (1.0f / EH) - mn * mn;
            mnE[a2] = mn; rsE[a2] = rsqrtf(vr + 1e-5f);
        }
    }
    __syncthreads();

    // eh hidden + output with folded LN
    {
        float acc[8];
#pragma unroll
        for (int k = 0; k < 8; k++) acc[k] = 0.0f;
#pragma unroll 4
        for (int m = 0; m < 64; m++) {
            float v = eb4[a * 68 + m];
            float4 wa = __ldg((const float4*)(d_ew1p + m * HD + h0));
            float4 wb = __ldg((const float4*)(d_ew1p + m * HD + h0 + 4));
            acc[0] = fmaf(v, wa.x, acc[0]); acc[1] = fmaf(v, wa.y, acc[1]);
            acc[2] = fmaf(v, wa.z, acc[2]); acc[3] = fmaf(v, wa.w, acc[3]);
            acc[4] = fmaf(v, wb.x, acc[4]); acc[5] = fmaf(v, wb.y, acc[5]);
            acc[6] = fmaf(v, wb.z, acc[6]); acc[7] = fmaf(v, wb.w, acc[7]);
        }
#pragma unroll 4
        for (int m = 0; m < SE; m++) {
            float v = s_sh[a * 97 + m];
            float4 wa = __ldg((const float4*)(d_ew1p + (64 + m) * HD + h0));
            float4 wb = __ldg((const float4*)(d_ew1p + (64 + m) * HD + h0 + 4));
            acc[0] = fmaf(v, wa.x, acc[0]); acc[1] = fmaf(v, wa.y, acc[1]);
            acc[2] = fmaf(v, wa.z, acc[2]); acc[3] = fmaf(v, wa.w, acc[3]);
            acc[4] = fmaf(v, wb.x, acc[4]); acc[5] = fmaf(v, wb.y, acc[5]);
            acc[6] = fmaf(v, wb.z, acc[6]); acc[7] = fmaf(v, wb.w, acc[7]);
        }
        float mn = mnE[a], rstd = rsE[a];
        float part = 0.0f;
#pragma unroll
        for (int hh = 0; hh < 8; hh++) {
            int h = h0 + hh;
            float pre = rstd * (acc[hh] - mn * __ldg(&d_c1h[h])) + __ldg(&d_c0h[h]) + __ldg(&eb1[h]);
            float sl = pre / (1.0f + expf(-pre));
            part = fmaf(sl, __ldg(&ew2[h]), part);
        }
        GRED(part);
        if (sub == 0) {
            float pa = part + __ldg(&eb2[0]);
            pa *= tanhf(__ldg(&far_gate[0])) * expf(__ldg(&escale[0]));
            d_pa[i0 + a] = pa;
        }
    }
}

// ---------------- K5: per-graph energy sum ----------------
__global__ __launch_bounds__(512) void reduce_kernel(float* __restrict__ out) {
    int g = blockIdx.x;
    int t = threadIdx.x;
    double v = (double)d_pa[g * NPG + t];
#pragma unroll
    for (int o = 16; o; o >>= 1) v += __shfl_xor_sync(0xffffffffu, v, o);
    __shared__ double sd[16];
    if ((t & 31) == 0) sd[t >> 5] = v;
    __syncthreads();
    if (t == 0) {
        double s = 0.0;
#pragma unroll
        for (int k = 0; k < 16; k++) s += sd[k];
        out[g] = (float)s;
    }
}

// ---------------- launcher ----------------
extern "C" void kernel_launch(void* const* d_in, const int* in_sizes, int n_in,
                              void* d_out, int out_size) {
    const float* x   = (const float*)d_in[0];
    const float* pos = (const float*)d_in[1];
    int idx = 3;
    if (idx < n_in && in_sizes[idx] == 1 && in_sizes[idx + 1] == FD) idx++;

    const float* in_ln_g = (const float*)d_in[idx++];
    const float* in_ln_b = (const float*)d_in[idx++];
    const float* src_w1  = (const float*)d_in[idx++];
    const float* src_b1  = (const float*)d_in[idx++];
    const float* src_w2  = (const float*)d_in[idx++];
    const float* src_b2  = (const float*)d_in[idx++];
    const float* src_lng = (const float*)d_in[idx++];
    const float* src_lnb = (const float*)d_in[idx++];
    const float* se_ln_g = (const float*)d_in[idx++];
    const float* se_ln_b = (const float*)d_in[idx++];
    const float* se_w1   = (const float*)d_in[idx++];
    const float* se_b1   = (const float*)d_in[idx++];
    const float* se_w2   = (const float*)d_in[idx++];
    const float* se_b2   = (const float*)d_in[idx++];
    const float* eh_ln_g = (const float*)d_in[idx++];
    const float* eh_ln_b = (const float*)d_in[idx++];
    const float* eh_w1   = (const float*)d_in[idx++];
    const float* eh_b1   = (const float*)d_in[idx++];
    const float* eh_w2   = (const float*)d_in[idx++];
    const float* eh_b2   = (const float*)d_in[idx++];
    const float* k_scr   = (const float*)d_in[idx++];
    const float* kg_w1   = (const float*)d_in[idx++];
    const float* kg_b1   = (const float*)d_in[idx++];
    const float* kg_w2   = (const float*)d_in[idx++];
    const float* kg_b2   = (const float*)d_in[idx++];
    const float* far_g   = (const float*)d_in[idx++];
    const float* e_scale = (const float*)d_in[idx++];

    table_kernel<<<(TABN2 + 256) / 256, 256>>>(k_scr, kg_w1, kg_b1, kg_w2, kg_b2);
    prep_kernel<<<3, HD>>>(in_ln_g, in_ln_b, src_w1, se_ln_g, se_ln_b, se_w1,
                           eh_ln_g, eh_ln_b, eh_w1);
    src_kernel<<<M_ATOMS / 32, 256>>>(x, src_b1, src_w2, src_b2, src_lng, src_lnb);
    mean_kernel<<<NB, 256>>>();
    pair_kernel<<<NB * 32, 128>>>(pos);
    energy_kernel<<<M_ATOMS / 32, 256>>>(se_b1, se_w2, se_b2, eh_b1, eh_w2, eh_b2,
                                         far_g, e_scale);
    reduce_kernel<<<NB, 512>>>((float*)d_out);
}

// round 4
// speedup vs baseline: 1.4203x; 1.4203x over previous
#include <cuda_runtime.h>
#include <cuda_bf16.h>
#include <math.h>

// ---------------- problem constants ----------------
#define M_ATOMS 8192
#define NB      16
#define NPG     512
#define FD      128
#define HD      64
#define DD      16
#define SE      95
#define EH      159
#define TABN2   8192
#define INVD2   59.0f        // covers d <= 138.8 (max possible ~138.6)
#define SPAD    20

// ---------------- device scratch ----------------
__device__ float  d_tabraw[TABN2 + 2];
__device__ float2 d_tab2[TABN2 + 1];
__device__ float d_srcraw[M_ATOMS * DD];
__device__ float d_gmean[NB * DD];
__device__ float d_shell[M_ATOMS * SE];
__device__ float d_pa[M_ATOMS];

// ---------------- scalar kernel function f(d) ----------------
__device__ __forceinline__ float kerf(float d, float scr,
                                      const float* kw1, const float* kb1,
                                      const float* kw2, const float* kb2) {
    float base = expf(-scr * d) / fmaxf(d, 1e-6f);
    float g0 = d * (1.0f / 5.0f);
    float g1 = d * (1.0f / 40.0f);
    float rbf[8];
#pragma unroll
    for (int r = 0; r < 8; r++) {
        float dc = d - (5.0f + 5.0f * (float)r);
        rbf[r] = expf(-0.04f * dc * dc);
    }
    float out = kb2[0];
#pragma unroll 4
    for (int k = 0; k < 32; k++) {
        float a = kb1[k];
        a = fmaf(g0, kw1[0 * 32 + k], a);
        a = fmaf(g1, kw1[1 * 32 + k], a);
#pragma unroll
        for (int r = 0; r < 8; r++) a = fmaf(rbf[r], kw1[(2 + r) * 32 + k], a);
        float sl = a / (1.0f + expf(-a));
        out = fmaf(sl, kw2[k], out);
    }
    return base * (1.0f + tanhf(out));
}

// ---------------- K0a: raw table values ----------------
__global__ void tableA_kernel(const float* __restrict__ k_screen,
                              const float* __restrict__ kw1, const float* __restrict__ kb1,
                              const float* __restrict__ kw2, const float* __restrict__ kb2) {
    int i = blockIdx.x * blockDim.x + threadIdx.x;
    if (i > TABN2 + 1) return;
    float scr = log1pf(expf(k_screen[0]));
    d_tabraw[i] = kerf((float)i / INVD2, scr, kw1, kb1, kw2, kb2);
}

// ---------------- K0b: (value, delta) pairs ----------------
__global__ void tableB_kernel() {
    int i = blockIdx.x * blockDim.x + threadIdx.x;
    if (i > TABN2) return;
    float f0 = d_tabraw[i];
    d_tab2[i] = make_float2(f0, d_tabraw[i + 1] - f0);
}

// ---------------- K1: per-atom source features (R2-measured version) ----------------
__global__ __launch_bounds__(128) void src_kernel(
    const float* __restrict__ x,
    const float* __restrict__ ing, const float* __restrict__ inb,
    const float* __restrict__ w1, const float* __restrict__ b1,
    const float* __restrict__ w2, const float* __restrict__ b2,
    const float* __restrict__ lg, const float* __restrict__ lb) {
    int i = blockIdx.x;
    int t = threadIdx.x;
    __shared__ float sh[FD];
    __shared__ float rs[4], rq[4];
    __shared__ float hid2[2][HD];
    __shared__ float hid[HD];
    __shared__ float ob[DD];

    float v = x[(size_t)i * FD + t];
    float s = v, q = v * v;
#pragma unroll
    for (int o = 16; o; o >>= 1) {
        s += __shfl_xor_sync(0xffffffffu, s, o);
        q += __shfl_xor_sync(0xffffffffu, q, o);
    }
    if ((t & 31) == 0) { rs[t >> 5] = s; rq[t >> 5] = q; }
    __syncthreads();
    s = rs[0] + rs[1] + rs[2] + rs[3];
    q = rq[0] + rq[1] + rq[2] + rq[3];
    float mean = s * (1.0f / FD);
    float var  = q * (1.0f / FD) - mean * mean;
    float rstd = rsqrtf(var + 1e-5f);
    sh[t] = (v - mean) * rstd * ing[t] + inb[t];
    __syncthreads();

    {   // hidden layer: split 128 input dims across 2 halves of the block
        int k = t & 63, half = t >> 6;
        float a = 0.0f;
        int m0 = half * 64;
#pragma unroll 8
        for (int m = 0; m < 64; m++) a = fmaf(sh[m0 + m], w1[(m0 + m) * HD + k], a);
        hid2[half][k] = a;
    }
    __syncthreads();
    if (t < HD) {
        float u = hid2[0][t] + hid2[1][t] + b1[t];
        hid[t] = u / (1.0f + expf(-u));
    }
    __syncthreads();
    if (t < DD) {
        float a = b2[t];
#pragma unroll 8
        for (int k = 0; k < HD; k++) a = fmaf(hid[k], w2[k * DD + t], a);
        ob[t] = a;
        __syncwarp(0x0000ffffu);
        float s2 = 0.0f, q2 = 0.0f;
#pragma unroll
        for (int c = 0; c < DD; c++) { float u = ob[c]; s2 += u; q2 += u * u; }
        float mn = s2 * (1.0f / DD);
        float vr = q2 * (1.0f / DD) - mn * mn;
        float y = (a - mn) * rsqrtf(vr + 1e-5f) * lg[t] + lb[t];
        d_srcraw[(size_t)i * DD + t] = y;
    }
}

// ---------------- K2: per-graph mean of src (fast warp version) ----------------
__global__ __launch_bounds__(512) void mean_kernel() {
    int g = blockIdx.x;
    int t = threadIdx.x;             // 512 = one atom per thread
    int w = t >> 5, lane = t & 31;
    const float4* row = (const float4*)(d_srcraw + (size_t)(g * NPG + t) * DD);
    float4 r0 = row[0], r1 = row[1], r2 = row[2], r3 = row[3];
    float v[16] = { r0.x, r0.y, r0.z, r0.w, r1.x, r1.y, r1.z, r1.w,
                    r2.x, r2.y, r2.z, r2.w, r3.x, r3.y, r3.z, r3.w };
#pragma unroll
    for (int c = 0; c < 16; c++) {
#pragma unroll
        for (int o = 16; o; o >>= 1) v[c] += __shfl_xor_sync(0xffffffffu, v[c], o);
    }
    __shared__ float sm[16][17];
    if (lane < 16) { /* lane0 holds all sums; broadcast write via lane0 only */ }
    if (lane == 0) {
#pragma unroll
        for (int c = 0; c < 16; c++) sm[w][c] = v[c];
    }
    __syncthreads();
    if (t < DD) {
        float s = 0.0f;
#pragma unroll
        for (int k = 0; k < 16; k++) s += sm[k][t];
        d_gmean[g * DD + t] = s * (1.0f / NPG);
    }
}

// ---------------- K3: pairwise shell statistics ----------------
// 256 thr = 8 warps; warp = 4 atoms x (4 j-lanes x 2 channel-halves)
#define GRED4(v) { v += __shfl_down_sync(0xffffffffu, v, 2); \
                   v += __shfl_down_sync(0xffffffffu, v, 1); }

__global__ __launch_bounds__(256, 2) void pair_kernel(const float* __restrict__ pos) {
    __shared__ float sTf[NPG * SPAD];
    __shared__ float px[NPG], py[NPG], pz[NPG];
    __shared__ float msh[DD];
    int g    = blockIdx.x >> 4;   // 16 blocks per graph
    int blk  = blockIdx.x & 15;   // 32 atoms per block
    int t    = threadIdx.x;
    int gbase = g * NPG;

    if (t < DD) msh[t] = d_gmean[g * DD + t];
    __syncthreads();
    for (int idx = t; idx < NPG * DD; idx += 256) {
        int j = idx >> 4, c = idx & 15;
        sTf[j * SPAD + c] = d_srcraw[(size_t)(gbase + j) * DD + c] - msh[c];
    }
    for (int j = t; j < NPG; j += 256) {
        const float* p = pos + (size_t)(gbase + j) * 3;
        px[j] = p[0]; py[j] = p[1]; pz[j] = p[2];
    }
    __syncthreads();

    int w = t >> 5, lane = t & 31;
    int a = lane >> 3, sub = lane & 7;
    int half = sub >> 2, jsub = sub & 3;
    int li = blk * 32 + w * 4 + a;
    float xi = px[li], yi = py[li], zi = pz[li];
    int c0 = half * 8;

    float am[40];
    float ac[5], ad[5], ad2[5];
#pragma unroll
    for (int c = 0; c < 40; c++) am[c] = 0.0f;
#pragma unroll
    for (int s = 0; s < 5; s++) { ac[s] = 0.f; ad[s] = 0.f; ad2[s] = 0.f; }

#pragma unroll 4
    for (int it = 0; it < 128; it++) {
        int j = jsub + it * 4;
        float dx = px[j] - xi, dy = py[j] - yi, dz = pz[j] - zi;
        float dsq = fmaf(dx, dx, fmaf(dy, dy, fmaf(dz, dz, 1e-12f)));
        float d = sqrtf(dsq);
        float tt = d * INVD2;
        int k = (int)tt; if (k > TABN2 - 1) k = TABN2 - 1;
        float fr = tt - (float)k;
        float2 tv = __ldg(&d_tab2[k]);
        float wv = fmaf(fr, tv.y, tv.x);
        float m0 = (d >= 5.0f  && d < 10.0f) ? 1.0f : 0.0f;
        float m1 = (d >= 10.0f && d < 20.0f) ? 1.0f : 0.0f;
        float m2 = (d >= 20.0f && d < 40.0f) ? 1.0f : 0.0f;
        float m3 = (d >= 40.0f && d < 80.0f) ? 1.0f : 0.0f;
        float m4 = (d >= 80.0f) ? 1.0f : 0.0f;
        float w0 = wv * m0, w1 = wv * m1, w2 = wv * m2, w3 = wv * m3, w4 = wv * m4;
        float dd = d * d;
        ac[0] += m0; ad[0] = fmaf(m0, d, ad[0]); ad2[0] = fmaf(m0, dd, ad2[0]);
        ac[1] += m1; ad[1] = fmaf(m1, d, ad[1]); ad2[1] = fmaf(m1, dd, ad2[1]);
        ac[2] += m2; ad[2] = fmaf(m2, d, ad[2]); ad2[2] = fmaf(m2, dd, ad2[2]);
        ac[3] += m3; ad[3] = fmaf(m3, d, ad[3]); ad2[3] = fmaf(m3, dd, ad2[3]);
        ac[4] += m4; ad[4] = fmaf(m4, d, ad[4]); ad2[4] = fmaf(m4, dd, ad2[4]);
        float4 s0 = *(const float4*)(sTf + j * SPAD + c0);
        float4 s1 = *(const float4*)(sTf + j * SPAD + c0 + 4);
        float sv[8] = { s0.x, s0.y, s0.z, s0.w, s1.x, s1.y, s1.z, s1.w };
#pragma unroll
        for (int c = 0; c < 8; c++) {
            am[0 * 8 + c] = fmaf(w0, sv[c], am[0 * 8 + c]);
            am[1 * 8 + c] = fmaf(w1, sv[c], am[1 * 8 + c]);
            am[2 * 8 + c] = fmaf(w2, sv[c], am[2 * 8 + c]);
            am[3 * 8 + c] = fmaf(w3, sv[c], am[3 * 8 + c]);
            am[4 * 8 + c] = fmaf(w4, sv[c], am[4 * 8 + c]);
        }
    }

    // reduce across the 4 j-lanes (valid at jsub==0 of each half)
#pragma unroll
    for (int s = 0; s < 5; s++) { GRED4(ac[s]); GRED4(ad[s]); GRED4(ad2[s]); }
#pragma unroll
    for (int c = 0; c < 40; c++) { GRED4(am[c]); }

    if (jsub == 0) {
        int i = gbase + li;
        float* o = d_shell + (size_t)i * SE;
#pragma unroll
        for (int s = 0; s < 5; s++) {
            float cnt = ac[s];
            float den = fmaxf(cnt, 1.0f);
            float inv = 1.0f / den;
#pragma unroll
            for (int c = 0; c < 8; c++) o[s * 19 + c0 + c] = am[s * 8 + c] * inv;
            if (half == 0) {
                o[s * 19 + 16] = cnt;
                o[s * 19 + 17] = ad[s] * inv;
                o[s * 19 + 18] = sqrtf(ad2[s] * inv + 1e-12f);
            }
        }
    }
}

// ---------------- K4: per-atom energy head (R2-measured version) ----------------
__global__ __launch_bounds__(64) void energy_kernel(
    const float* __restrict__ seg, const float* __restrict__ seb,
    const float* __restrict__ sw1, const float* __restrict__ sb1,
    const float* __restrict__ sw2, const float* __restrict__ sb2,
    const float* __restrict__ eg,  const float* __restrict__ ebv,
    const float* __restrict__ ew1, const float* __restrict__ eb1,
    const float* __restrict__ ew2, const float* __restrict__ eb2,
    const float* __restrict__ far_gate, const float* __restrict__ escale) {
    int i = blockIdx.x;
    int t = threadIdx.x;   // 64
    int g = i >> 9;
    __shared__ float shell[SE];
    __shared__ float buf[EH];
    __shared__ float nb[EH];
    __shared__ float hid[HD];
    __shared__ float srcc[DD];
    __shared__ float embs[DD];
    __shared__ float rs[2], rq[2], pr[2];

    for (int idx = t; idx < SE; idx += 64) shell[idx] = d_shell[(size_t)i * SE + idx];
    if (t < DD) srcc[t] = d_srcraw[(size_t)i * DD + t] - d_gmean[g * DD + t];
    __syncthreads();

    // LayerNorm(shell, 95)
    float s = 0.0f, q = 0.0f;
    for (int idx = t; idx < SE; idx += 64) { float v = shell[idx]; s += v; q += v * v; }
#pragma unroll
    for (int o = 16; o; o >>= 1) {
        s += __shfl_xor_sync(0xffffffffu, s, o);
        q += __shfl_xor_sync(0xffffffffu, q, o);
    }
    if ((t & 31) == 0) { rs[t >> 5] = s; rq[t >> 5] = q; }
    __syncthreads();
    s = rs[0] + rs[1]; q = rq[0] + rq[1];
    {
        float mn = s * (1.0f / SE);
        float vr = q * (1.0f / SE) - mn * mn;
        float rstd = rsqrtf(vr + 1e-5f);
        for (int idx = t; idx < SE; idx += 64)
            nb[idx] = (shell[idx] - mn) * rstd * seg[idx] + seb[idx];
    }
    __syncthreads();

    {   // se MLP hidden
        float a2 = sb1[t];
#pragma unroll 5
        for (int m = 0; m < SE; m++) a2 = fmaf(nb[m], sw1[m * HD + t], a2);
        hid[t] = a2 / (1.0f + expf(-a2));
    }
    __syncthreads();
    if (t < DD) {
        float e = sb2[t];
#pragma unroll 8
        for (int k = 0; k < HD; k++) e = fmaf(hid[k], sw2[k * DD + t], e);
        embs[t] = e;
    }
    __syncthreads();

    // build ein = [src, emb, src*emb, src-emb, shell]
    if (t < DD) {
        float sc = srcc[t], e = embs[t];
        buf[t] = sc; buf[16 + t] = e; buf[32 + t] = sc * e; buf[48 + t] = sc - e;
    }
    for (int idx = t; idx < SE; idx += 64) buf[64 + idx] = shell[idx];
    __syncthreads();

    // LayerNorm(ein, 159)
    s = 0.0f; q = 0.0f;
    for (int idx = t; idx < EH; idx += 64) { float v = buf[idx]; s += v; q += v * v; }
#pragma unroll
    for (int o = 16; o; o >>= 1) {
        s += __shfl_xor_sync(0xffffffffu, s, o);
        q += __shfl_xor_sync(0xffffffffu, q, o);
    }
    if ((t & 31) == 0) { rs[t >> 5] = s; rq[t >> 5] = q; }
    __syncthreads();
    s = rs[0] + rs[1]; q = rq[0] + rq[1];
    {
        float mn = s * (1.0f / EH);
        float vr = q * (1.0f / EH) - mn * mn;
        float rstd = rsqrtf(vr + 1e-5f);
        for (int idx = t; idx < EH; idx += 64)
            nb[idx] = (buf[idx] - mn) * rstd * eg[idx] + ebv[idx];
    }
    __syncthreads();

    {   // eh MLP hidden + output
        float a2 = eb1[t];
#pragma unroll 3
        for (int m = 0; m < EH; m++) a2 = fmaf(nb[m], ew1[m * HD + t], a2);
        a2 = a2 / (1.0f + expf(-a2));
        float part = a2 * ew2[t];
#pragma unroll
        for (int o = 16; o; o >>= 1) part += __shfl_xor_sync(0xffffffffu, part, o);
        if ((t & 31) == 0) pr[t >> 5] = part;
    }
    __syncthreads();
    if (t == 0) {
        float pa = pr[0] + pr[1] + eb2[0];
        pa *= tanhf(far_gate[0]) * expf(escale[0]);
        d_pa[i] = pa;
    }
}

// ---------------- K5: per-graph energy sum ----------------
__global__ __launch_bounds__(512) void reduce_kernel(float* __restrict__ out) {
    int g = blockIdx.x;
    int t = threadIdx.x;
    double v = (double)d_pa[g * NPG + t];
#pragma unroll
    for (int o = 16; o; o >>= 1) v += __shfl_xor_sync(0xffffffffu, v, o);
    __shared__ double sd[16];
    if ((t & 31) == 0) sd[t >> 5] = v;
    __syncthreads();
    if (t == 0) {
        double s = 0.0;
#pragma unroll
        for (int k = 0; k < 16; k++) s += sd[k];
        out[g] = (float)s;
    }
}

// ---------------- launcher (self-locating input map) ----------------
extern "C" void kernel_launch(void* const* d_in, const int* in_sizes, int n_in,
                              void* d_out, int out_size) {
    const float* x   = (const float*)d_in[0];
    const float* pos = (const float*)d_in[1];
    int idx = 3;
    if (idx < n_in && in_sizes[idx] == 1 && in_sizes[idx + 1] == FD) idx++;

    const float* in_ln_g = (const float*)d_in[idx++];
    const float* in_ln_b = (const float*)d_in[idx++];
    const float* src_w1  = (const float*)d_in[idx++];
    const float* src_b1  = (const float*)d_in[idx++];
    const float* src_w2  = (const float*)d_in[idx++];
    const float* src_b2  = (const float*)d_in[idx++];
    const float* src_lng = (const float*)d_in[idx++];
    const float* src_lnb = (const float*)d_in[idx++];
    const float* se_ln_g = (const float*)d_in[idx++];
    const float* se_ln_b = (const float*)d_in[idx++];
    const float* se_w1   = (const float*)d_in[idx++];
    const float* se_b1   = (const float*)d_in[idx++];
    const float* se_w2   = (const float*)d_in[idx++];
    const float* se_b2   = (const float*)d_in[idx++];
    const float* eh_ln_g = (const float*)d_in[idx++];
    const float* eh_ln_b = (const float*)d_in[idx++];
    const float* eh_w1   = (const float*)d_in[idx++];
    const float* eh_b1   = (const float*)d_in[idx++];
    const float* eh_w2   = (const float*)d_in[idx++];
    const float* eh_b2   = (const float*)d_in[idx++];
    const float* k_scr   = (const float*)d_in[idx++];
    const float* kg_w1   = (const float*)d_in[idx++];
    const float* kg_b1   = (const float*)d_in[idx++];
    const float* kg_w2   = (const float*)d_in[idx++];
    const float* kg_b2   = (const float*)d_in[idx++];
    const float* far_g   = (const float*)d_in[idx++];
    const float* e_scale = (const float*)d_in[idx++];

    tableA_kernel<<<(TABN2 + 2 + 255) / 256, 256>>>(k_scr, kg_w1, kg_b1, kg_w2, kg_b2);
    tableB_kernel<<<(TABN2 + 1 + 255) / 256, 256>>>();
    src_kernel<<<M_ATOMS, 128>>>(x, in_ln_g, in_ln_b, src_w1, src_b1, src_w2, src_b2, src_lng, src_lnb);
    mean_kernel<<<NB, 512>>>();
    pair_kernel<<<NB * 16, 256>>>(pos);
    energy_kernel<<<M_ATOMS, 64>>>(se_ln_g, se_ln_b, se_w1, se_b1, se_w2, se_b2,
                                   eh_ln_g, eh_ln_b, eh_w1, eh_b1, eh_w2, eh_b2,
                                   far_g, e_scale);
    reduce_kernel<<<NB, 512>>>((float*)d_out);
}

// round 7
// speedup vs baseline: 1.6531x; 1.1639x over previous
#include <cuda_runtime.h>
#include <cuda_bf16.h>
#include <math.h>

// ---------------- problem constants ----------------
#define M_ATOMS 8192
#define NB      16
#define NPG     512
#define FD      128
#define HD      64
#define DD      16
#define SE      95
#define EH      159
#define TABN2   8192
#define INVD2   59.0f
#define SPAD    20
#define TPAD    20   // small-tile row stride (floats); 80B = 16B-aligned

// ---------------- device scratch ----------------
__device__ float  d_tabraw[TABN2 + 2];
__device__ float2 d_tab2[TABN2 + 1];
__device__ float d_srcraw[M_ATOMS * DD];
__device__ float d_gmean[NB * DD];
__device__ float d_shell[M_ATOMS * SE];
__device__ float d_pa[M_ATOMS];

// ---------------- scalar kernel function f(d) ----------------
__device__ __forceinline__ float kerf(float d, float scr,
                                      const float* kw1, const float* kb1,
                                      const float* kw2, const float* kb2) {
    float base = expf(-scr * d) / fmaxf(d, 1e-6f);
    float g0 = d * (1.0f / 5.0f);
    float g1 = d * (1.0f / 40.0f);
    float rbf[8];
#pragma unroll
    for (int r = 0; r < 8; r++) {
        float dc = d - (5.0f + 5.0f * (float)r);
        rbf[r] = expf(-0.04f * dc * dc);
    }
    float out = kb2[0];
#pragma unroll 4
    for (int k = 0; k < 32; k++) {
        float a = kb1[k];
        a = fmaf(g0, kw1[0 * 32 + k], a);
        a = fmaf(g1, kw1[1 * 32 + k], a);
#pragma unroll
        for (int r = 0; r < 8; r++) a = fmaf(rbf[r], kw1[(2 + r) * 32 + k], a);
        float sl = a / (1.0f + expf(-a));
        out = fmaf(sl, kw2[k], out);
    }
    return base * (1.0f + tanhf(out));
}

__global__ void tableA_kernel(const float* __restrict__ k_screen,
                              const float* __restrict__ kw1, const float* __restrict__ kb1,
                              const float* __restrict__ kw2, const float* __restrict__ kb2) {
    int i = blockIdx.x * blockDim.x + threadIdx.x;
    if (i > TABN2 + 1) return;
    float scr = log1pf(expf(k_screen[0]));
    d_tabraw[i] = kerf((float)i / INVD2, scr, kw1, kb1, kw2, kb2);
}

__global__ void tableB_kernel() {
    int i = blockIdx.x * blockDim.x + threadIdx.x;
    if (i > TABN2) return;
    float f0 = d_tabraw[i];
    d_tab2[i] = make_float2(f0, d_tabraw[i + 1] - f0);
}

// ---------------- K1: source MLP as register-blocked GEMM ----------------
// 64 atoms/block, 256 threads (16x16), 4x4 accumulators.
// smem floats: As[128*68]=8704, hs[64*68]=4352, os[64*20]=1280, ps[256], pq[256], mnv[64], rsv[64]
#define SRC_SMEM_FLOATS (8704 + 4352 + 1280 + 256 + 256 + 64 + 64)

__global__ __launch_bounds__(256) void src_gemm_kernel(
    const float* __restrict__ x,
    const float* __restrict__ ing, const float* __restrict__ inb,
    const float* __restrict__ w1, const float* __restrict__ b1,
    const float* __restrict__ w2, const float* __restrict__ b2,
    const float* __restrict__ lg, const float* __restrict__ lb) {
    extern __shared__ float sm[];
    float* As  = sm;
    float* hs  = As + 8704;
    float* os  = hs + 4352;
    float* ps  = os + 1280;
    float* pq  = ps + 256;
    float* mnv = pq + 256;
    float* rsv = mnv + 64;

    int t = threadIdx.x;
    int row4 = t >> 2, lane4 = t & 3;
    int i0 = blockIdx.x * 64;

    // pass1: row stats
    const float4* xr = (const float4*)(x + (size_t)(i0 + row4) * FD);
    float s = 0.0f, q = 0.0f;
#pragma unroll
    for (int i = 0; i < 8; i++) {
        float4 v = xr[lane4 + 4 * i];
        s += v.x + v.y + v.z + v.w;
        q += v.x * v.x + v.y * v.y + v.z * v.z + v.w * v.w;
    }
    ps[t] = s; pq[t] = q;
    __syncthreads();
    if (t < 64) {
        float ss = ps[4 * t] + ps[4 * t + 1] + ps[4 * t + 2] + ps[4 * t + 3];
        float qq = pq[4 * t] + pq[4 * t + 1] + pq[4 * t + 2] + pq[4 * t + 3];
        float mn = ss * (1.0f / FD);
        float vr = qq * (1.0f / FD) - mn * mn;
        mnv[t] = mn; rsv[t] = rsqrtf(vr + 1e-5f);
    }
    __syncthreads();

    // pass2: build normalized A (k-major)
    {
        float mn = mnv[row4], rstd = rsv[row4];
#pragma unroll
        for (int i = 0; i < 8; i++) {
            float4 v = xr[lane4 + 4 * i];
            int k0 = (lane4 + 4 * i) * 4;
            As[(k0 + 0) * 68 + row4] = (v.x - mn) * rstd * __ldg(&ing[k0 + 0]) + __ldg(&inb[k0 + 0]);
            As[(k0 + 1) * 68 + row4] = (v.y - mn) * rstd * __ldg(&ing[k0 + 1]) + __ldg(&inb[k0 + 1]);
            As[(k0 + 2) * 68 + row4] = (v.z - mn) * rstd * __ldg(&ing[k0 + 2]) + __ldg(&inb[k0 + 2]);
            As[(k0 + 3) * 68 + row4] = (v.w - mn) * rstd * __ldg(&ing[k0 + 3]) + __ldg(&inb[k0 + 3]);
        }
    }
    __syncthreads();

    // GEMM: 128 x (64x64)
    int tx = t & 15, ty = t >> 4;
    float acc[4][4];
#pragma unroll
    for (int r = 0; r < 4; r++)
#pragma unroll
        for (int c = 0; c < 4; c++) acc[r][c] = 0.0f;
#pragma unroll 4
    for (int k = 0; k < FD; k++) {
        float4 a = *(const float4*)&As[k * 68 + 4 * ty];
        float4 b = __ldg((const float4*)(w1 + k * HD + 4 * tx));
        float av[4] = { a.x, a.y, a.z, a.w };
        float bv[4] = { b.x, b.y, b.z, b.w };
#pragma unroll
        for (int r = 0; r < 4; r++)
#pragma unroll
            for (int c = 0; c < 4; c++) acc[r][c] = fmaf(av[r], bv[c], acc[r][c]);
    }
    {
        float4 bb = __ldg((const float4*)(b1 + 4 * tx));
        float bv[4] = { bb.x, bb.y, bb.z, bb.w };
#pragma unroll
        for (int r = 0; r < 4; r++) {
            float4 hv;
            float p0 = acc[r][0] + bv[0]; hv.x = p0 / (1.0f + expf(-p0));
            float p1 = acc[r][1] + bv[1]; hv.y = p1 / (1.0f + expf(-p1));
            float p2 = acc[r][2] + bv[2]; hv.z = p2 / (1.0f + expf(-p2));
            float p3 = acc[r][3] + bv[3]; hv.w = p3 / (1.0f + expf(-p3));
            *(float4*)&hs[(4 * ty + r) * 68 + 4 * tx] = hv;
        }
    }
    __syncthreads();

    // layer2: 64 -> 16, row4/lane4 (4 outs each)
    {
        float4 bb = __ldg((const float4*)(b2 + lane4 * 4));
        float accO[4] = { bb.x, bb.y, bb.z, bb.w };
#pragma unroll 4
        for (int k = 0; k < HD; k++) {
            float h = hs[row4 * 68 + k];
            float4 w = __ldg((const float4*)(w2 + k * DD + lane4 * 4));
            accO[0] = fmaf(h, w.x, accO[0]); accO[1] = fmaf(h, w.y, accO[1]);
            accO[2] = fmaf(h, w.z, accO[2]); accO[3] = fmaf(h, w.w, accO[3]);
        }
        *(float4*)&os[row4 * TPAD + lane4 * 4] = make_float4(accO[0], accO[1], accO[2], accO[3]);
    }
    __syncthreads();

    // LN(16)
    if (t < 64) {
        float ss = 0.0f, qq = 0.0f;
#pragma unroll
        for (int c = 0; c < DD; c++) { float v = os[t * TPAD + c]; ss += v; qq += v * v; }
        float mn = ss * (1.0f / DD);
        float vr = qq * (1.0f / DD) - mn * mn;
        mnv[t] = mn; rsv[t] = rsqrtf(vr + 1e-5f);
    }
    __syncthreads();
    {
        float mn = mnv[row4], rstd = rsv[row4];
        float4 g4 = __ldg((const float4*)(lg + lane4 * 4));
        float4 b4 = __ldg((const float4*)(lb + lane4 * 4));
        float4 o4 = *(const float4*)&os[row4 * TPAD + lane4 * 4];
        float4 y;
        y.x = (o4.x - mn) * rstd * g4.x + b4.x;
        y.y = (o4.y - mn) * rstd * g4.y + b4.y;
        y.z = (o4.z - mn) * rstd * g4.z + b4.z;
        y.w = (o4.w - mn) * rstd * g4.w + b4.w;
        *(float4*)&d_srcraw[(size_t)(i0 + row4) * DD + lane4 * 4] = y;
    }
}

// ---------------- K2: per-graph mean of src ----------------
__global__ __launch_bounds__(512) void mean_kernel() {
    int g = blockIdx.x;
    int t = threadIdx.x;
    int w = t >> 5, lane = t & 31;
    const float4* row = (const float4*)(d_srcraw + (size_t)(g * NPG + t) * DD);
    float4 r0 = row[0], r1 = row[1], r2 = row[2], r3 = row[3];
    float v[16] = { r0.x, r0.y, r0.z, r0.w, r1.x, r1.y, r1.z, r1.w,
                    r2.x, r2.y, r2.z, r2.w, r3.x, r3.y, r3.z, r3.w };
#pragma unroll
    for (int c = 0; c < 16; c++) {
#pragma unroll
        for (int o = 16; o; o >>= 1) v[c] += __shfl_xor_sync(0xffffffffu, v[c], o);
    }
    __shared__ float smn[16][17];
    if (lane == 0) {
#pragma unroll
        for (int c = 0; c < 16; c++) smn[w][c] = v[c];
    }
    __syncthreads();
    if (t < DD) {
        float s = 0.0f;
#pragma unroll
        for (int k = 0; k < 16; k++) s += smn[k][t];
        d_gmean[g * DD + t] = s * (1.0f / NPG);
    }
}

// ---------------- K3: pairwise shell statistics (R4-measured version) ----------------
#define GRED4(v) { v += __shfl_down_sync(0xffffffffu, v, 2); \
                   v += __shfl_down_sync(0xffffffffu, v, 1); }

__global__ __launch_bounds__(256, 2) void pair_kernel(const float* __restrict__ pos) {
    __shared__ float sTf[NPG * SPAD];
    __shared__ float px[NPG], py[NPG], pz[NPG];
    __shared__ float msh[DD];
    int g    = blockIdx.x >> 4;
    int blk  = blockIdx.x & 15;
    int t    = threadIdx.x;
    int gbase = g * NPG;

    if (t < DD) msh[t] = d_gmean[g * DD + t];
    __syncthreads();
    for (int idx = t; idx < NPG * DD; idx += 256) {
        int j = idx >> 4, c = idx & 15;
        sTf[j * SPAD + c] = d_srcraw[(size_t)(gbase + j) * DD + c] - msh[c];
    }
    for (int j = t; j < NPG; j += 256) {
        const float* p = pos + (size_t)(gbase + j) * 3;
        px[j] = p[0]; py[j] = p[1]; pz[j] = p[2];
    }
    __syncthreads();

    int w = t >> 5, lane = t & 31;
    int a = lane >> 3, sub = lane & 7;
    int half = sub >> 2, jsub = sub & 3;
    int li = blk * 32 + w * 4 + a;
    float xi = px[li], yi = py[li], zi = pz[li];
    int c0 = half * 8;

    float am[40];
    float ac[5], ad[5], ad2[5];
#pragma unroll
    for (int c = 0; c < 40; c++) am[c] = 0.0f;
#pragma unroll
    for (int s = 0; s < 5; s++) { ac[s] = 0.f; ad[s] = 0.f; ad2[s] = 0.f; }

#pragma unroll 4
    for (int it = 0; it < 128; it++) {
        int j = jsub + it * 4;
        float dx = px[j] - xi, dy = py[j] - yi, dz = pz[j] - zi;
        float dsq = fmaf(dx, dx, fmaf(dy, dy, fmaf(dz, dz, 1e-12f)));
        float d = sqrtf(dsq);
        float tt = d * INVD2;
        int k = (int)tt; if (k > TABN2 - 1) k = TABN2 - 1;
        float fr = tt - (float)k;
        float2 tv = __ldg(&d_tab2[k]);
        float wv = fmaf(fr, tv.y, tv.x);
        float m0 = (d >= 5.0f  && d < 10.0f) ? 1.0f : 0.0f;
        float m1 = (d >= 10.0f && d < 20.0f) ? 1.0f : 0.0f;
        float m2 = (d >= 20.0f && d < 40.0f) ? 1.0f : 0.0f;
        float m3 = (d >= 40.0f && d < 80.0f) ? 1.0f : 0.0f;
        float m4 = (d >= 80.0f) ? 1.0f : 0.0f;
        float w0 = wv * m0, w1 = wv * m1, w2 = wv * m2, w3 = wv * m3, w4 = wv * m4;
        float dd = d * d;
        ac[0] += m0; ad[0] = fmaf(m0, d, ad[0]); ad2[0] = fmaf(m0, dd, ad2[0]);
        ac[1] += m1; ad[1] = fmaf(m1, d, ad[1]); ad2[1] = fmaf(m1, dd, ad2[1]);
        ac[2] += m2; ad[2] = fmaf(m2, d, ad[2]); ad2[2] = fmaf(m2, dd, ad2[2]);
        ac[3] += m3; ad[3] = fmaf(m3, d, ad[3]); ad2[3] = fmaf(m3, dd, ad2[3]);
        ac[4] += m4; ad[4] = fmaf(m4, d, ad[4]); ad2[4] = fmaf(m4, dd, ad2[4]);
        float4 s0 = *(const float4*)(sTf + j * SPAD + c0);
        float4 s1 = *(const float4*)(sTf + j * SPAD + c0 + 4);
        float sv[8] = { s0.x, s0.y, s0.z, s0.w, s1.x, s1.y, s1.z, s1.w };
#pragma unroll
        for (int c = 0; c < 8; c++) {
            am[0 * 8 + c] = fmaf(w0, sv[c], am[0 * 8 + c]);
            am[1 * 8 + c] = fmaf(w1, sv[c], am[1 * 8 + c]);
            am[2 * 8 + c] = fmaf(w2, sv[c], am[2 * 8 + c]);
            am[3 * 8 + c] = fmaf(w3, sv[c], am[3 * 8 + c]);
            am[4 * 8 + c] = fmaf(w4, sv[c], am[4 * 8 + c]);
        }
    }

#pragma unroll
    for (int s = 0; s < 5; s++) { GRED4(ac[s]); GRED4(ad[s]); GRED4(ad2[s]); }
#pragma unroll
    for (int c = 0; c < 40; c++) { GRED4(am[c]); }

    if (jsub == 0) {
        int i = gbase + li;
        float* o = d_shell + (size_t)i * SE;
#pragma unroll
        for (int s = 0; s < 5; s++) {
            float cnt = ac[s];
            float den = fmaxf(cnt, 1.0f);
            float inv = 1.0f / den;
#pragma unroll
            for (int c = 0; c < 8; c++) o[s * 19 + c0 + c] = am[s * 8 + c] * inv;
            if (half == 0) {
                o[s * 19 + 16] = cnt;
                o[s * 19 + 17] = ad[s] * inv;
                o[s * 19 + 18] = sqrtf(ad2[s] * inv + 1e-12f);
            }
        }
    }
}

// ---------------- K4: energy head as register-blocked GEMMs ----------------
// 64 atoms/block, 256 threads (16x16).
// smem floats: As[159*68]=10812, hs[64*68]=4352, sc[64*20]=1280, es[64*20]=1280,
// part[64*20]=1280, ps[256], pq[256], sumS..rsE 6*64
#define EGY_SMEM_FLOATS (10812 + 4352 + 1280 + 1280 + 1280 + 256 + 256 + 64 * 6)

__global__ __launch_bounds__(256) void energy_gemm_kernel(
    const float* __restrict__ seg, const float* __restrict__ seb,
    const float* __restrict__ sw1, const float* __restrict__ sb1,
    const float* __restrict__ sw2, const float* __restrict__ sb2,
    const float* __restrict__ eg,  const float* __restrict__ ebv,
    const float* __restrict__ ew1, const float* __restrict__ eb1,
    const float* __restrict__ ew2, const float* __restrict__ eb2,
    const float* __restrict__ far_gate, const float* __restrict__ escale) {
    extern __shared__ float sm[];
    float* As   = sm;
    float* hs   = As + 10812;
    float* sc   = hs + 4352;
    float* es   = sc + 1280;
    float* part = es + 1280;
    float* ps   = part + 1280;
    float* pq   = ps + 256;
    float* sumS = pq + 256;
    float* qS   = sumS + 64;
    float* mnS  = qS + 64;
    float* rsS  = mnS + 64;
    float* mnE  = rsS + 64;
    float* rsE  = mnE + 64;

    int t = threadIdx.x;
    int row4 = t >> 2, lane4 = t & 3;
    int i0 = blockIdx.x * 64;
    int g = i0 >> 9;
    const float* shrow = d_shell + (size_t)(i0 + row4) * SE;

    // shell row stats
    {
        float s = 0.0f, q = 0.0f;
        for (int i = 0; i < 24; i++) {
            int k = lane4 + 4 * i;
            if (k < SE) { float v = __ldg(&shrow[k]); s += v; q += v * v; }
        }
        ps[t] = s; pq[t] = q;
    }
    // centered src tile
    {
        float4 sv = __ldg((const float4*)(d_srcraw + (size_t)(i0 + row4) * DD + lane4 * 4));
        float4 gm = __ldg((const float4*)(d_gmean + g * DD + lane4 * 4));
        sv.x -= gm.x; sv.y -= gm.y; sv.z -= gm.z; sv.w -= gm.w;
        *(float4*)&sc[row4 * TPAD + lane4 * 4] = sv;
    }
    __syncthreads();
    if (t < 64) {
        float ss = ps[4 * t] + ps[4 * t + 1] + ps[4 * t + 2] + ps[4 * t + 3];
        float qq = pq[4 * t] + pq[4 * t + 1] + pq[4 * t + 2] + pq[4 * t + 3];
        sumS[t] = ss; qS[t] = qq;
        float mn = ss * (1.0f / SE);
        float vr = qq * (1.0f / SE) - mn * mn;
        mnS[t] = mn; rsS[t] = rsqrtf(vr + 1e-5f);
    }
    __syncthreads();

    // build As1 = LN(shell) with se_ln (k-major, 95 rows)
    {
        float mn = mnS[row4], rstd = rsS[row4];
        for (int i = 0; i < 24; i++) {
            int k = lane4 + 4 * i;
            if (k < SE) {
                float v = __ldg(&shrow[k]);
                As[k * 68 + row4] = (v - mn) * rstd * __ldg(&seg[k]) + __ldg(&seb[k]);
            }
        }
    }
    __syncthreads();

    int tx = t & 15, ty = t >> 4;
    // GEMM1: 95 -> 64
    {
        float acc[4][4];
#pragma unroll
        for (int r = 0; r < 4; r++)
#pragma unroll
            for (int c = 0; c < 4; c++) acc[r][c] = 0.0f;
        for (int k = 0; k < SE; k++) {
            float4 a = *(const float4*)&As[k * 68 + 4 * ty];
            float4 b = __ldg((const float4*)(sw1 + k * HD + 4 * tx));
            float av[4] = { a.x, a.y, a.z, a.w };
            float bv[4] = { b.x, b.y, b.z, b.w };
#pragma unroll
            for (int r = 0; r < 4; r++)
#pragma unroll
                for (int c = 0; c < 4; c++) acc[r][c] = fmaf(av[r], bv[c], acc[r][c]);
        }
        float4 bb = __ldg((const float4*)(sb1 + 4 * tx));
        float bv[4] = { bb.x, bb.y, bb.z, bb.w };
#pragma unroll
        for (int r = 0; r < 4; r++) {
            float4 hv;
            float p0 = acc[r][0] + bv[0]; hv.x = p0 / (1.0f + expf(-p0));
            float p1 = acc[r][1] + bv[1]; hv.y = p1 / (1.0f + expf(-p1));
            float p2 = acc[r][2] + bv[2]; hv.z = p2 / (1.0f + expf(-p2));
            float p3 = acc[r][3] + bv[3]; hv.w = p3 / (1.0f + expf(-p3));
            *(float4*)&hs[(4 * ty + r) * 68 + 4 * tx] = hv;
        }
    }
    __syncthreads();

    // emb = hid @ sw2 + sb2
    {
        float4 bb = __ldg((const float4*)(sb2 + lane4 * 4));
        float accO[4] = { bb.x, bb.y, bb.z, bb.w };
#pragma unroll 4
        for (int k = 0; k < HD; k++) {
            float h = hs[row4 * 68 + k];
            float4 w = __ldg((const float4*)(sw2 + k * DD + lane4 * 4));
            accO[0] = fmaf(h, w.x, accO[0]); accO[1] = fmaf(h, w.y, accO[1]);
            accO[2] = fmaf(h, w.z, accO[2]); accO[3] = fmaf(h, w.w, accO[3]);
        }
        *(float4*)&es[row4 * TPAD + lane4 * 4] = make_float4(accO[0], accO[1], accO[2], accO[3]);
    }
    __syncthreads();

    // ein stats: 64-dim part per row + shell sums
    {
        float s = 0.0f, q = 0.0f;
#pragma unroll
        for (int cc = 0; cc < 4; cc++) {
            int c = lane4 * 4 + cc;
            float sv = sc[row4 * TPAD + c], ev = es[row4 * TPAD + c];
            float pv = sv * ev, dv = sv - ev;
            s += sv + ev + pv + dv;
            q += sv * sv + ev * ev + pv * pv + dv * dv;
        }
        ps[t] = s; pq[t] = q;
    }
    __syncthreads();
    if (t < 64) {
        float ss = ps[4 * t] + ps[4 * t + 1] + ps[4 * t + 2] + ps[4 * t + 3] + sumS[t];
        float qq = pq[4 * t] + pq[4 * t + 1] + pq[4 * t + 2] + pq[4 * t + 3] + qS[t];
        float mn = ss * (1.0f / EH);
        float vr = qq * (1.0f / EH) - mn * mn;
        mnE[t] = mn; rsE[t] = rsqrtf(vr + 1e-5f);
    }
    __syncthreads();

    // build As2 = LN(ein) with eh_ln (k-major, 159 rows)
    {
        float mn = mnE[row4], rstd = rsE[row4];
#pragma unroll
        for (int cc = 0; cc < 4; cc++) {
            int c = lane4 * 4 + cc;
            float sv = sc[row4 * TPAD + c], ev = es[row4 * TPAD + c];
            float vals[4] = { sv, ev, sv * ev, sv - ev };
#pragma unroll
            for (int sgm = 0; sgm < 4; sgm++) {
                int k = sgm * 16 + c;
                As[k * 68 + row4] = (vals[sgm] - mn) * rstd * __ldg(&eg[k]) + __ldg(&ebv[k]);
            }
        }
        for (int i = 0; i < 24; i++) {
            int kk = lane4 + 4 * i;
            if (kk < SE) {
                int k = 64 + kk;
                float v = __ldg(&shrow[kk]);
                As[k * 68 + row4] = (v - mn) * rstd * __ldg(&eg[k]) + __ldg(&ebv[k]);
            }
        }
    }
    __syncthreads();

    // GEMM2: 159 -> 64, silu, dot with ew2
    {
        float acc[4][4];
#pragma unroll
        for (int r = 0; r < 4; r++)
#pragma unroll
            for (int c = 0; c < 4; c++) acc[r][c] = 0.0f;
        for (int k = 0; k < EH; k++) {
            float4 a = *(const float4*)&As[k * 68 + 4 * ty];
            float4 b = __ldg((const float4*)(ew1 + k * HD + 4 * tx));
            float av[4] = { a.x, a.y, a.z, a.w };
            float bv[4] = { b.x, b.y, b.z, b.w };
#pragma unroll
            for (int r = 0; r < 4; r++)
#pragma unroll
                for (int c = 0; c < 4; c++) acc[r][c] = fmaf(av[r], bv[c], acc[r][c]);
        }
        float4 bb = __ldg((const float4*)(eb1 + 4 * tx));
        float4 w2v = __ldg((const float4*)(ew2 + 4 * tx));
        float bv[4] = { bb.x, bb.y, bb.z, bb.w };
        float wv[4] = { w2v.x, w2v.y, w2v.z, w2v.w };
#pragma unroll
        for (int r = 0; r < 4; r++) {
            float rp = 0.0f;
#pragma unroll
            for (int c = 0; c < 4; c++) {
                float pre = acc[r][c] + bv[c];
                float sl = pre / (1.0f + expf(-pre));
                rp = fmaf(sl, wv[c], rp);
            }
            part[(4 * ty + r) * TPAD + tx] = rp;
        }
    }
    __syncthreads();
    if (t < 64) {
        float s = 0.0f;
#pragma unroll
        for (int k = 0; k < 16; k++) s += part[t * TPAD + k];
        float pa = s + __ldg(&eb2[0]);
        pa *= tanhf(__ldg(&far_gate[0])) * expf(__ldg(&escale[0]));
        d_pa[i0 + t] = pa;
    }
}

// ---------------- K5: per-graph energy sum ----------------
__global__ __launch_bounds__(512) void reduce_kernel(float* __restrict__ out) {
    int g = blockIdx.x;
    int t = threadIdx.x;
    double v = (double)d_pa[g * NPG + t];
#pragma unroll
    for (int o = 16; o; o >>= 1) v += __shfl_xor_sync(0xffffffffu, v, o);
    __shared__ double sd[16];
    if ((t & 31) == 0) sd[t >> 5] = v;
    __syncthreads();
    if (t == 0) {
        double s = 0.0;
#pragma unroll
        for (int k = 0; k < 16; k++) s += sd[k];
        out[g] = (float)s;
    }
}

// ---------------- launcher ----------------
extern "C" void kernel_launch(void* const* d_in, const int* in_sizes, int n_in,
                              void* d_out, int out_size) {
    const float* x   = (const float*)d_in[0];
    const float* pos = (const float*)d_in[1];
    int idx = 3;
    if (idx < n_in && in_sizes[idx] == 1 && in_sizes[idx + 1] == FD) idx++;

    const float* in_ln_g = (const float*)d_in[idx++];
    const float* in_ln_b = (const float*)d_in[idx++];
    const float* src_w1  = (const float*)d_in[idx++];
    const float* src_b1  = (const float*)d_in[idx++];
    const float* src_w2  = (const float*)d_in[idx++];
    const float* src_b2  = (const float*)d_in[idx++];
    const float* src_lng = (const float*)d_in[idx++];
    const float* src_lnb = (const float*)d_in[idx++];
    const float* se_ln_g = (const float*)d_in[idx++];
    const float* se_ln_b = (const float*)d_in[idx++];
    const float* se_w1   = (const float*)d_in[idx++];
    const float* se_b1   = (const float*)d_in[idx++];
    const float* se_w2   = (const float*)d_in[idx++];
    const float* se_b2   = (const float*)d_in[idx++];
    const float* eh_ln_g = (const float*)d_in[idx++];
    const float* eh_ln_b = (const float*)d_in[idx++];
    const float* eh_w1   = (const float*)d_in[idx++];
    const float* eh_b1   = (const float*)d_in[idx++];
    const float* eh_w2   = (const float*)d_in[idx++];
    const float* eh_b2   = (const float*)d_in[idx++];
    const float* k_scr   = (const float*)d_in[idx++];
    const float* kg_w1   = (const float*)d_in[idx++];
    const float* kg_b1   = (const float*)d_in[idx++];
    const float* kg_w2   = (const float*)d_in[idx++];
    const float* kg_b2   = (const float*)d_in[idx++];
    const float* far_g   = (const float*)d_in[idx++];
    const float* e_scale = (const float*)d_in[idx++];

    cudaFuncSetAttribute(src_gemm_kernel, cudaFuncAttributeMaxDynamicSharedMemorySize,
                         SRC_SMEM_FLOATS * 4);
    cudaFuncSetAttribute(energy_gemm_kernel, cudaFuncAttributeMaxDynamicSharedMemorySize,
                         EGY_SMEM_FLOATS * 4);

    tableA_kernel<<<(TABN2 + 2 + 255) / 256, 256>>>(k_scr, kg_w1, kg_b1, kg_w2, kg_b2);
    tableB_kernel<<<(TABN2 + 1 + 255) / 256, 256>>>();
    src_gemm_kernel<<<M_ATOMS / 64, 256, SRC_SMEM_FLOATS * 4>>>(
        x, in_ln_g, in_ln_b, src_w1, src_b1, src_w2, src_b2, src_lng, src_lnb);
    mean_kernel<<<NB, 512>>>();
    pair_kernel<<<NB * 16, 256>>>(pos);
    energy_gemm_kernel<<<M_ATOMS / 64, 256, EGY_SMEM_FLOATS * 4>>>(
        se_ln_g, se_ln_b, se_w1, se_b1, se_w2, se_b2,
        eh_ln_g, eh_ln_b, eh_w1, eh_b1, eh_w2, eh_b2, far_g, e_scale);
    reduce_kernel<<<NB, 512>>>((float*)d_out);
}